// round 5
// baseline (speedup 1.0000x reference)
#include <cuda_runtime.h>
#include <cuda_fp16.h>
#include <cstdint>

// Problem dims
#define S_DIM   32
#define B_DIM   256
#define IN_DIM  1024
#define OUT_DIM 1024

// ---------------------------------------------------------------------------
// Scratch (device globals; the only sanctioned scratch)
// ---------------------------------------------------------------------------
__device__ __align__(128) __half g_wf16[(size_t)S_DIM * OUT_DIM * IN_DIM];  // 67 MB
__device__ __align__(128) __half g_xf16[(size_t)S_DIM * B_DIM * IN_DIM];    // 17 MB

__device__ __forceinline__ float softplusf(float x) {
    return (x > 15.0f) ? x : log1pf(expf(x));
}

__device__ __forceinline__ uint32_t smem_to_u32(const void* smem_ptr) {
    uint32_t addr;
    asm("{ .reg .u64 tmp; cvta.to.shared.u64 tmp, %1; cvt.u32.u64 %0, tmp; }"
        : "=r"(addr) : "l"(smem_ptr));
    return addr;
}

__device__ __forceinline__ void cp_async16(uint32_t smem_dst, const void* gptr) {
    asm volatile("cp.async.cg.shared.global [%0], [%1], 16;"
                 :: "r"(smem_dst), "l"(gptr) : "memory");
}

__device__ __forceinline__ void ldmatrix_x4(uint32_t r[4], uint32_t addr) {
    asm volatile("ldmatrix.sync.aligned.m8n8.x4.shared.b16 {%0,%1,%2,%3}, [%4];"
                 : "=r"(r[0]), "=r"(r[1]), "=r"(r[2]), "=r"(r[3]) : "r"(addr));
}

__device__ __forceinline__ void mma16816(float c[4],
                                         const uint32_t a[4],
                                         uint32_t b0, uint32_t b1) {
    asm volatile(
        "mma.sync.aligned.m16n8k16.row.col.f32.f16.f16.f32 "
        "{%0,%1,%2,%3}, {%4,%5,%6,%7}, {%8,%9}, {%0,%1,%2,%3};"
        : "+f"(c[0]), "+f"(c[1]), "+f"(c[2]), "+f"(c[3])
        : "r"(a[0]), "r"(a[1]), "r"(a[2]), "r"(a[3]), "r"(b0), "r"(b1));
}

// SW128 swizzle: byte address of 16B-quad (row, colq) in a 128-row x 128B tile.
// XOR applied to the FINAL column-quad index.
__device__ __forceinline__ uint32_t sw128(int row, int colq) {
    return ((uint32_t)row << 7) + ((uint32_t)((colq ^ (row & 7)) & 7) << 4);
}

// ---------------------------------------------------------------------------
// Kernel 1: w_f16[s,o,i] = half(mu[o,i] + softplus(rho[o,i]) * eps_w[s,o,i])
// One thread owns one (o,i) float4-quad; loads mu/rho ONCE, loops all 32 s.
// ---------------------------------------------------------------------------
__global__ __launch_bounds__(256)
void prep_w_kernel(const float* __restrict__ wmu,
                   const float* __restrict__ wrho,
                   const float* __restrict__ epsw)
{
    const int q  = blockIdx.x * 256 + threadIdx.x;   // 0 .. 262143 quads
    const int mi = q * 4;                            // element idx in (OUT,IN)

    const float4 m = *reinterpret_cast<const float4*>(wmu + mi);
    const float4 r = *reinterpret_cast<const float4*>(wrho + mi);
    float4 sg;
    sg.x = softplusf(r.x);
    sg.y = softplusf(r.y);
    sg.z = softplusf(r.z);
    sg.w = softplusf(r.w);

    const size_t plane = (size_t)OUT_DIM * IN_DIM;
    #pragma unroll 4
    for (int s = 0; s < S_DIM; ++s) {
        const float4 ew = *reinterpret_cast<const float4*>(epsw + s * plane + mi);
        float w0 = fmaf(sg.x, ew.x, m.x);
        float w1 = fmaf(sg.y, ew.y, m.y);
        float w2 = fmaf(sg.z, ew.z, m.z);
        float w3 = fmaf(sg.w, ew.w, m.w);
        __half2 h0 = __floats2half2_rn(w0, w1);
        __half2 h1 = __floats2half2_rn(w2, w3);
        uint2 o;
        o.x = *reinterpret_cast<unsigned*>(&h0);
        o.y = *reinterpret_cast<unsigned*>(&h1);
        *reinterpret_cast<uint2*>(g_wf16 + s * plane + mi) = o;
    }
}

// ---------------------------------------------------------------------------
// Kernel 2: x_f16 = (half) input
// ---------------------------------------------------------------------------
__global__ __launch_bounds__(256)
void prep_x_kernel(const float* __restrict__ input)
{
    const int e4 = blockIdx.x * 256 + threadIdx.x;   // 0 .. 2097151
    const size_t e = (size_t)e4 * 4;
    const float4 x = *reinterpret_cast<const float4*>(input + e);
    __half2 h0 = __floats2half2_rn(x.x, x.y);
    __half2 h1 = __floats2half2_rn(x.z, x.w);
    uint2 o;
    o.x = *reinterpret_cast<unsigned*>(&h0);
    o.y = *reinterpret_cast<unsigned*>(&h1);
    reinterpret_cast<uint2*>(g_xf16)[e4] = o;
}

// ---------------------------------------------------------------------------
// Kernel 3: per-sample GEMM via mma.sync (HMMA, fp16 in / fp32 accum).
// CTA tile M=128 (batch) x N=128 (out), K=1024 in 16 chunks of 64.
// 8 warps (2x4): warp tile 64x32 -> 4x4 mma.m16n8k16 per k16 step.
// Both operands stream via cp.async.cg into a 2-stage SW128 double buffer.
// Grid: (ntile=8, mtile=2, s=32) = 512 CTAs, 256 threads.
// ---------------------------------------------------------------------------
#define KC 64
#define NCHUNK (IN_DIM / KC)          // 16
#define TILE_BYTES (128 * 128)        // 16 KB = 1024 16B-quads per tile
#define STAGE_BYTES (2 * TILE_BYTES)  // A + B per stage
#define GEMM_DYN_SMEM (1024 + 2 * STAGE_BYTES)

__global__ __launch_bounds__(256)
void gemm_f16_kernel(const float* __restrict__ bias_mu,
                     const float* __restrict__ bias_rho,
                     const float* __restrict__ eps_b,
                     float* __restrict__ out)
{
    extern __shared__ char dynsmem[];
    __shared__ float s_bias[128];

    const int tid = threadIdx.x;
    const int wid = tid >> 5;
    const int lid = tid & 31;
    const int ntile = blockIdx.x;   // 0..7
    const int mtile = blockIdx.y;   // 0..1
    const int s     = blockIdx.z;   // 0..31

    uint32_t base = smem_to_u32(dynsmem);
    base = (base + 1023u) & ~1023u;
    const uint32_t smA0 = base;
    const uint32_t smB0 = base + TILE_BYTES;

    // Fused bias: bias(s,o) = bias_mu[o] + softplus(bias_rho[o]) * eps_b[s,o]
    if (tid < 128) {
        const int o = ntile * 128 + tid;
        s_bias[tid] = fmaf(softplusf(bias_rho[o]), eps_b[s * OUT_DIM + o], bias_mu[o]);
    }

    const __half* Ag = g_xf16 + (size_t)(s * B_DIM + mtile * 128) * IN_DIM;
    const __half* Bg = g_wf16 + (size_t)(s * OUT_DIM + ntile * 128) * IN_DIM;

    // Per-thread copy slots: 4 quads per tile per thread (256*4 = 1024 quads
    // = the FULL 16KB tile).
    int cp_row[4], cp_kq[4];
    uint32_t cp_dst[4];
    #pragma unroll
    for (int j = 0; j < 4; ++j) {
        const int q = tid + j * 256;  // 0..1023
        cp_row[j] = q >> 3;           // 0..127
        cp_kq[j]  = q & 7;            // 16B quad within 128B row
        cp_dst[j] = sw128(cp_row[j], cp_kq[j]);
    }

    // Warp tiling: 2 (M) x 4 (N) warps; warp tile 64 x 32.
    const int wm_idx = wid >> 2;      // 0..1
    const int wn_idx = wid & 3;       // 0..3

    // ldmatrix per-lane row and base column-quad (swizzle applied per k-step).
    int a_row[4];
    #pragma unroll
    for (int mi = 0; mi < 4; ++mi)
        a_row[mi] = wm_idx * 64 + mi * 16 + (lid & 15);
    const int a_cq0 = (lid >> 4);     // 0 or 1

    int b_row[2];
    #pragma unroll
    for (int g = 0; g < 2; ++g)
        b_row[g] = wn_idx * 32 + g * 16 + ((lid >> 4) << 3) + (lid & 7);
    const int b_cq0 = ((lid >> 3) & 1);

    float acc[4][4][4];
    #pragma unroll
    for (int mi = 0; mi < 4; ++mi)
        #pragma unroll
        for (int ni = 0; ni < 4; ++ni)
            #pragma unroll
            for (int k = 0; k < 4; ++k)
                acc[mi][ni][k] = 0.0f;

    // Issue copies for chunk c into stage st (full 16KB per tile).
    auto issue_chunk = [&](int c, int st) {
        const int kb = c * KC;
        const uint32_t sa = smA0 + (uint32_t)st * STAGE_BYTES;
        const uint32_t sb = smB0 + (uint32_t)st * STAGE_BYTES;
        #pragma unroll
        for (int j = 0; j < 4; ++j) {
            const size_t go = (size_t)cp_row[j] * IN_DIM + kb + cp_kq[j] * 8;
            cp_async16(sa + cp_dst[j], Ag + go);
            cp_async16(sb + cp_dst[j], Bg + go);
        }
        asm volatile("cp.async.commit_group;" ::: "memory");
    };

    issue_chunk(0, 0);
    issue_chunk(1, 1);

    for (int c = 0; c < NCHUNK; ++c) {
        const int st = c & 1;
        // Last chunk has no successor group in flight: must drain fully.
        if (c == NCHUNK - 1) {
            asm volatile("cp.async.wait_group 0;" ::: "memory");
        } else {
            asm volatile("cp.async.wait_group 1;" ::: "memory");
        }
        __syncthreads();

        const uint32_t sa = smA0 + (uint32_t)st * STAGE_BYTES;
        const uint32_t sb = smB0 + (uint32_t)st * STAGE_BYTES;

        #pragma unroll
        for (int ks = 0; ks < 4; ++ks) {
            uint32_t ar[4][4];
            uint32_t br[2][4];
            #pragma unroll
            for (int mi = 0; mi < 4; ++mi)
                ldmatrix_x4(ar[mi], sa + sw128(a_row[mi], a_cq0 + 2 * ks));
            #pragma unroll
            for (int g = 0; g < 2; ++g)
                ldmatrix_x4(br[g], sb + sw128(b_row[g], b_cq0 + 2 * ks));

            #pragma unroll
            for (int mi = 0; mi < 4; ++mi) {
                #pragma unroll
                for (int ni = 0; ni < 4; ++ni) {
                    const int g = ni >> 1;
                    const int h = (ni & 1) << 1;   // 0 or 2
                    mma16816(acc[mi][ni], ar[mi], br[g][h + 0], br[g][h + 1]);
                }
            }
        }

        __syncthreads();
        if (c + 2 < NCHUNK) issue_chunk(c + 2, st);
    }

    // Epilogue: D fragment: d0,d1 = [r][c,c+1], d2,d3 = [r+8][c,c+1]
    // with r = lid>>2, c = (lid&3)*2 within each 16x8 mma tile. Add bias, store.
    const int row_in = (lid >> 2);
    const int col_in = (lid & 3) * 2;
    #pragma unroll
    for (int mi = 0; mi < 4; ++mi) {
        const int m0 = mtile * 128 + wm_idx * 64 + mi * 16 + row_in;
        float* orow0 = out + ((size_t)(s * B_DIM + m0)     * OUT_DIM) + ntile * 128;
        float* orow1 = out + ((size_t)(s * B_DIM + m0 + 8) * OUT_DIM) + ntile * 128;
        #pragma unroll
        for (int ni = 0; ni < 4; ++ni) {
            const int lcol = wn_idx * 32 + ni * 8 + col_in;
            const float b0 = s_bias[lcol];
            const float b1 = s_bias[lcol + 1];
            float2 v0, v1;
            v0.x = acc[mi][ni][0] + b0;
            v0.y = acc[mi][ni][1] + b1;
            v1.x = acc[mi][ni][2] + b0;
            v1.y = acc[mi][ni][3] + b1;
            *reinterpret_cast<float2*>(orow0 + lcol) = v0;
            *reinterpret_cast<float2*>(orow1 + lcol) = v1;
        }
    }
}

// ---------------------------------------------------------------------------
// Launch
// ---------------------------------------------------------------------------
extern "C" void kernel_launch(void* const* d_in, const int* in_sizes, int n_in,
                              void* d_out, int out_size)
{
    (void)in_sizes; (void)n_in; (void)out_size;
    const float* input  = (const float*)d_in[0];
    const float* wmu    = (const float*)d_in[1];
    const float* wrho   = (const float*)d_in[2];
    const float* bmu    = (const float*)d_in[3];
    const float* brho   = (const float*)d_in[4];
    const float* epsw   = (const float*)d_in[5];
    const float* epsb   = (const float*)d_in[6];
    float* out = (float*)d_out;

    cudaFuncSetAttribute(gemm_f16_kernel,
                         cudaFuncAttributeMaxDynamicSharedMemorySize,
                         GEMM_DYN_SMEM);

    // 262,144 (o,i)-quads; each thread loops 32 samples
    prep_w_kernel<<<1024, 256>>>(wmu, wrho, epsw);
    // 2,097,152 input quads
    prep_x_kernel<<<8192, 256>>>(input);
    // (ntile=8, mtile=2, s=32) = 512 CTAs
    gemm_f16_kernel<<<dim3(8, 2, 32), 256, GEMM_DYN_SMEM>>>(bmu, brho, epsb, out);
}